// round 4
// baseline (speedup 1.0000x reference)
#include <cuda_runtime.h>
#include <cuda_bf16.h>

// Resample2d bilinear warp — direct gather with aligned-float4 row fetch.
// input1: [8,64,384,512] f32, input2(flow): [8,2,384,512] f32, out NCHW f32.
//
// R2 (213us): 4 scalar gathers/channel, L1tex 82.8% binding (x0 and x0+1
// gathers double-count the same sectors). R3 smem staging regressed (L1 work
// amplified). This round: per row fetch ONE aligned float4 at xa=x0&~3
// (covers x0,x0+1 unless x0%4==3), plus a predicated scalar for the 25%
// straddle lanes. Blend via 5 precomputed per-component weights -> FMA dot,
// no dynamic indexing, zero-weight terms exact.

#define B_ 8
#define D_ 64
#define H_ 384
#define W_ 512
#define PLANE_ (H_ * W_)
#define TPB 256

__global__ __launch_bounds__(TPB)
void resample2d_kernel(const float* __restrict__ img,
                       const float* __restrict__ flow,
                       float* __restrict__ out)
{
    const int WCHUNKS = W_ / TPB;            // 2
    int bid = blockIdx.x;
    const int wchunk = bid % WCHUNKS;
    bid /= WCHUNKS;
    const int h = bid % H_;
    const int b = bid / H_;
    const int w = wchunk * TPB + threadIdx.x;

    // flow [B,2,H,W]
    const unsigned foff = (unsigned)b * (2u * PLANE_) + (unsigned)h * W_ + w;
    const float u = __ldg(flow + foff);
    const float v = __ldg(flow + foff + PLANE_);

    float fx = (float)w + u;
    float fy = (float)h + v;
    fx = fminf(fmaxf(fx, 0.0f), (float)(W_ - 1));
    fy = fminf(fmaxf(fy, 0.0f), (float)(H_ - 1));
    const int x0 = min((int)fx, W_ - 2);
    const int y0 = min((int)fy, H_ - 2);
    const float wx = fx - (float)x0;
    const float wy = fy - (float)y0;
    const float wy0 = 1.0f - wy;

    // aligned base + component weights (per-thread constants)
    const int xa = x0 & ~3;
    const int k  = x0 & 3;
    const float wx0 = 1.0f - wx;
    const float cw0 = (k == 0) ? wx0 : 0.0f;
    const float cw1 = (k == 1) ? wx0 : ((k == 0) ? wx : 0.0f);
    const float cw2 = (k == 2) ? wx0 : ((k == 1) ? wx : 0.0f);
    const float cw3 = (k == 3) ? wx0 : ((k == 2) ? wx : 0.0f);
    const float cw4 = (k == 3) ? wx  : 0.0f;
    const bool straddle = (k == 3);

    // 32-bit element offsets (tensor = 100.6M elems < 2^31)
    unsigned oa = (unsigned)b * (D_ * PLANE_) + (unsigned)y0 * W_ + (unsigned)xa;
    unsigned oo = (unsigned)b * (D_ * PLANE_) + (unsigned)h * W_ + (unsigned)w;

    #pragma unroll 4
    for (int d = 0; d < D_; ++d) {
        const float4 A0 = __ldg((const float4*)(img + oa));        // row y0
        const float4 A1 = __ldg((const float4*)(img + oa + W_));   // row y0+1
        float e0 = 0.0f, e1 = 0.0f;
        if (straddle) {
            e0 = __ldg(img + oa + 4);
            e1 = __ldg(img + oa + W_ + 4);
        }
        float dot0 = A0.x * cw0;
        dot0 = fmaf(A0.y, cw1, dot0);
        dot0 = fmaf(A0.z, cw2, dot0);
        dot0 = fmaf(A0.w, cw3, dot0);
        dot0 = fmaf(e0,   cw4, dot0);
        float dot1 = A1.x * cw0;
        dot1 = fmaf(A1.y, cw1, dot1);
        dot1 = fmaf(A1.z, cw2, dot1);
        dot1 = fmaf(A1.w, cw3, dot1);
        dot1 = fmaf(e1,   cw4, dot1);
        out[oo] = fmaf(wy, dot1, wy0 * dot0);

        oa += PLANE_;
        oo += PLANE_;
    }
}

extern "C" void kernel_launch(void* const* d_in, const int* in_sizes, int n_in,
                              void* d_out, int out_size)
{
    const float* img  = (const float*)d_in[0];
    const float* flow = (const float*)d_in[1];
    float* out = (float*)d_out;

    dim3 grid(B_ * H_ * (W_ / TPB));
    dim3 block(TPB);
    resample2d_kernel<<<grid, block>>>(img, flow, out);
}

// round 5
// speedup vs baseline: 1.5252x; 1.5252x over previous
#include <cuda_runtime.h>
#include <cuda_bf16.h>

// Resample2d bilinear warp — 2D-tiled smem staging, scalar coalesced loads.
// input1: [8,64,384,512] f32, input2(flow): [8,2,384,512], out NCHW f32.
//
// Calibrated wavefront model (R2-R4): scalar gathers ~12.5 wf each (distinct
// 128B lines), divergent vector gathers ~per-lane (bad), coalesced vector ops
// bytes/128. R2 (213us) = 4 scalar gathers/ch = ~55 wf/warp-ch, L1tex-bound.
// This kernel: block = 8h x 64w; per channel stage rows [h0-3,h0+11] x cols
// [w0-8,w0+71] (15x80, border-clamped content) into smem with scalar
// coalesced LDG/STS (offsets precomputed once), double-buffered, 1 barrier
// per channel. Gather via LDS (stride 81: row offsets distinct mod 32).
// ~13 wf/warp-ch. Lanes outside tile (~0.3%) use identical global path.

#define B_ 8
#define D_ 64
#define H_ 384
#define W_ 512
#define PLANE_ (H_ * W_)
#define TPB 512
#define BH 8        // rows per block
#define BW 64       // cols per block
#define MY 3        // row margin (top); bottom margin = 15-8-3 = 4
#define MX 8        // col margin
#define NR 15       // staged rows
#define NC 80       // staged cols
#define SSTR 81     // smem row stride (81 % 32 = 17 -> rows distinct banks)
#define TILE_ (NR * SSTR)

__global__ __launch_bounds__(TPB)
void resample2d_kernel(const float* __restrict__ img,
                       const float* __restrict__ flow,
                       float* __restrict__ out)
{
    __shared__ float tile[2][TILE_];

    const int tid = threadIdx.x;
    int gx = blockIdx.x;
    const int wb = gx & 7;          // W_/BW = 8
    gx >>= 3;
    const int hb = gx % (H_ / BH);  // 48
    const int b  = gx / (H_ / BH);
    const int h0 = hb * BH;
    const int w0 = wb * BW;

    const int h = h0 + (tid >> 6);        // tid/64
    const int w = w0 + (tid & 63);

    // ---- flow / weights / indices (once per thread) ----
    const unsigned foff = (unsigned)b * (2u * PLANE_) + (unsigned)h * W_ + w;
    const float u = __ldg(flow + foff);
    const float v = __ldg(flow + foff + PLANE_);

    float fx = (float)w + u;
    float fy = (float)h + v;
    fx = fminf(fmaxf(fx, 0.0f), (float)(W_ - 1));
    fy = fminf(fmaxf(fy, 0.0f), (float)(H_ - 1));
    const int x0 = min((int)fx, W_ - 2);
    const int y0 = min((int)fy, H_ - 2);
    const float wx = fx - (float)x0;
    const float wy = fy - (float)y0;

    const float w00 = (1.0f - wy) * (1.0f - wx);
    const float w01 = (1.0f - wy) * wx;
    const float w10 = wy * (1.0f - wx);
    const float w11 = wy * wx;

    // ---- staging geometry ----
    const int ylo = h0 - MY;              // may be <0; content is clamped
    const int xlo = w0 - MX;              // may be <0

    const bool ok = (y0 >= ylo) & (y0 - ylo <= NR - 2) &
                    (x0 >= xlo) & (x0 - xlo <= NC - 2);
    const int sb = (y0 - ylo) * SSTR + (x0 - xlo);

    // precomputed staging slots (loop-invariant across channels)
    int goff[3], soff[3];
    int nslots = 0;
    #pragma unroll
    for (int k = 0; k < 3; ++k) {
        const int idx = tid + k * TPB;
        if (idx < NR * NC) {
            const int r = idx / NC;
            const int c = idx - r * NC;
            const int gy = min(max(ylo + r, 0), H_ - 1);
            const int gxc = min(max(xlo + c, 0), W_ - 1);
            goff[k] = gy * W_ + gxc;
            soff[k] = r * SSTR + c;
            nslots = k + 1;
        }
    }

    const float* ip = img + (size_t)b * (D_ * PLANE_);   // batch base
    unsigned oo = (unsigned)b * (D_ * PLANE_) + (unsigned)h * W_ + (unsigned)w;

    // stage channel 0 into tile[0]
    {
        float t0 = __ldg(ip + goff[0]);
        float t1 = __ldg(ip + goff[1]);
        float t2 = (nslots > 2) ? __ldg(ip + goff[2]) : 0.0f;
        tile[0][soff[0]] = t0;
        tile[0][soff[1]] = t1;
        if (nslots > 2) tile[0][soff[2]] = t2;
    }
    __syncthreads();

    for (int d = 0; d < D_; ++d) {
        // stage next channel into the other buffer (overwrites buffer last
        // read at iteration d-1; end-of-iteration barrier ordered that).
        if (d + 1 < D_) {
            const float* ipn = ip + (size_t)(d + 1) * PLANE_;
            float t0 = __ldg(ipn + goff[0]);
            float t1 = __ldg(ipn + goff[1]);
            float t2 = (nslots > 2) ? __ldg(ipn + goff[2]) : 0.0f;
            float* tb = tile[(d + 1) & 1];
            tb[soff[0]] = t0;
            tb[soff[1]] = t1;
            if (nslots > 2) tb[soff[2]] = t2;
        }

        // gather + blend for channel d
        float a00, a01, a10, a11;
        if (ok) {
            const float* tb = tile[d & 1];
            a00 = tb[sb];
            a01 = tb[sb + 1];
            a10 = tb[sb + SSTR];
            a11 = tb[sb + SSTR + 1];
        } else {
            const float* ipd = ip + (size_t)d * PLANE_;
            const unsigned o0 = (unsigned)y0 * W_ + (unsigned)x0;
            a00 = __ldg(ipd + o0);
            a01 = __ldg(ipd + o0 + 1);
            a10 = __ldg(ipd + o0 + W_);
            a11 = __ldg(ipd + o0 + W_ + 1);
        }
        float r = w00 * a00;
        r = fmaf(w01, a01, r);
        r = fmaf(w10, a10, r);
        r = fmaf(w11, a11, r);
        out[oo] = r;
        oo += PLANE_;

        __syncthreads();
    }
}

extern "C" void kernel_launch(void* const* d_in, const int* in_sizes, int n_in,
                              void* d_out, int out_size)
{
    const float* img  = (const float*)d_in[0];
    const float* flow = (const float*)d_in[1];
    float* out = (float*)d_out;

    dim3 grid((W_ / BW) * (H_ / BH) * B_);   // 8 * 48 * 8 = 3072
    dim3 block(TPB);
    resample2d_kernel<<<grid, block>>>(img, flow, out);
}

// round 6
// speedup vs baseline: 2.3346x; 1.5307x over previous
#include <cuda_runtime.h>
#include <cuda_bf16.h>

// Resample2d bilinear warp — direct gather, x-pair merged via aligned LDG.64.
// input1: [8,64,384,512] f32, input2(flow): [8,2,384,512] f32, out NCHW f32.
//
// Evidence (R2-R5): DRAM work is ~100us-equiv in every variant (traffic
// minimal); binder is L1tex wavefronts. Direct scalar gather (R2, 213us) pays
// the same distinct-line set twice for x0 and x0+1. Divergent LDG.128 pays
// per-lane (R4, 3x worse). Smem staging does MORE L1 work (R3/R5). Fix here:
// one 8B-aligned LDG.64 per row at xe = x0 & ~1 (even -> never crosses a
// 128B line) covers (x0, x0+1) when x0 even; odd lanes (50%) add a predicated
// scalar load for x0+1. Branch-free SEL blend; streaming stores.

#define B_ 8
#define D_ 64
#define H_ 384
#define W_ 512
#define PLANE_ (H_ * W_)
#define TPB 256

__global__ __launch_bounds__(TPB)
void resample2d_kernel(const float* __restrict__ img,
                       const float* __restrict__ flow,
                       float* __restrict__ out)
{
    const int WCHUNKS = W_ / TPB;            // 2
    int bid = blockIdx.x;
    const int wchunk = bid % WCHUNKS;
    bid /= WCHUNKS;
    const int h = bid % H_;
    const int b = bid / H_;
    const int w = wchunk * TPB + threadIdx.x;

    // flow [B,2,H,W]
    const unsigned foff = (unsigned)b * (2u * PLANE_) + (unsigned)h * W_ + w;
    const float u = __ldg(flow + foff);
    const float v = __ldg(flow + foff + PLANE_);

    float fx = (float)w + u;
    float fy = (float)h + v;
    fx = fminf(fmaxf(fx, 0.0f), (float)(W_ - 1));
    fy = fminf(fmaxf(fy, 0.0f), (float)(H_ - 1));
    const int x0 = min((int)fx, W_ - 2);
    const int y0 = min((int)fy, H_ - 2);
    const float wx = fx - (float)x0;
    const float wy = fy - (float)y0;

    const float w00 = (1.0f - wy) * (1.0f - wx);
    const float w01 = (1.0f - wy) * wx;
    const float w10 = wy * (1.0f - wx);
    const float w11 = wy * wx;

    const int xe = x0 & ~1;                  // even -> 8B-aligned LDG.64
    const bool odd = (x0 & 1);

    // 32-bit element offsets (tensor = 100.6M elems < 2^31)
    unsigned oe = (unsigned)b * (D_ * PLANE_) + (unsigned)y0 * W_ + (unsigned)xe;
    unsigned oo = (unsigned)b * (D_ * PLANE_) + (unsigned)h * W_ + (unsigned)w;

    #pragma unroll 8
    for (int d = 0; d < D_; ++d) {
        const float2 pA = __ldg((const float2*)(img + oe));        // row y0: (xe, xe+1)
        const float2 pB = __ldg((const float2*)(img + oe + W_));   // row y0+1
        float eA = 0.0f, eB = 0.0f;
        if (odd) {                                                 // x0+1 == xe+2
            eA = __ldg(img + oe + 2);
            eB = __ldg(img + oe + W_ + 2);
        }
        const float a00 = odd ? pA.y : pA.x;
        const float a01 = odd ? eA   : pA.y;
        const float a10 = odd ? pB.y : pB.x;
        const float a11 = odd ? eB   : pB.y;

        float r = w00 * a00;
        r = fmaf(w01, a01, r);
        r = fmaf(w10, a10, r);
        r = fmaf(w11, a11, r);
        __stcs(out + oo, r);

        oe += PLANE_;
        oo += PLANE_;
    }
}

extern "C" void kernel_launch(void* const* d_in, const int* in_sizes, int n_in,
                              void* d_out, int out_size)
{
    const float* img  = (const float*)d_in[0];
    const float* flow = (const float*)d_in[1];
    float* out = (float*)d_out;

    dim3 grid(B_ * H_ * (W_ / TPB));
    dim3 block(TPB);
    resample2d_kernel<<<grid, block>>>(img, flow, out);
}

// round 7
// speedup vs baseline: 2.6971x; 1.1553x over previous
#include <cuda_runtime.h>
#include <cuda_bf16.h>

// Resample2d bilinear warp — scalar direct gather, 2 independent pixels/thread.
// input1: [8,64,384,512] f32, input2(flow): [8,2,384,512] f32, out NCHW f32.
//
// Calibration across R1-R6: binder is l1tex wavefronts; scalar LDG.32 gathers
// are wf-optimal (divergent LDG.64 ~1.4x, LDG.128 ~3x per line-set; smem
// staging adds pipe work; quad/shuffle schemes lose 32-px line amortization).
// R2 (213us) = the optimal shape at L1=83.8%, issue 20% -> pipe underfed.
// This round: each thread handles pixels (w, w+256) of its row -> two
// independent gather chains, 2x outstanding loads, identical per-instruction
// warp footprint (lanes still span 32 consecutive x per gather).

#define B_ 8
#define D_ 64
#define H_ 384
#define W_ 512
#define PLANE_ (H_ * W_)
#define TPB 256

__global__ __launch_bounds__(TPB)
void resample2d_kernel(const float* __restrict__ img,
                       const float* __restrict__ flow,
                       float* __restrict__ out)
{
    const int h = blockIdx.x % H_;
    const int b = blockIdx.x / H_;
    const int w = threadIdx.x;               // pixel A: w ; pixel B: w + 256

    // ---- flow [B,2,H,W] ----
    const unsigned fbase = (unsigned)b * (2u * PLANE_) + (unsigned)h * W_;
    const float uA = __ldg(flow + fbase + w);
    const float uB = __ldg(flow + fbase + w + 256);
    const float vA = __ldg(flow + fbase + PLANE_ + w);
    const float vB = __ldg(flow + fbase + PLANE_ + w + 256);

    // ---- pixel A indices/weights ----
    float fxA = (float)w + uA;
    float fyA = (float)h + vA;
    fxA = fminf(fmaxf(fxA, 0.0f), (float)(W_ - 1));
    fyA = fminf(fmaxf(fyA, 0.0f), (float)(H_ - 1));
    const int x0A = min((int)fxA, W_ - 2);
    const int y0A = min((int)fyA, H_ - 2);
    const float wxA = fxA - (float)x0A;
    const float wyA = fyA - (float)y0A;
    const float w00A = (1.0f - wyA) * (1.0f - wxA);
    const float w01A = (1.0f - wyA) * wxA;
    const float w10A = wyA * (1.0f - wxA);
    const float w11A = wyA * wxA;

    // ---- pixel B indices/weights ----
    float fxB = (float)(w + 256) + uB;
    float fyB = (float)h + vB;
    fxB = fminf(fmaxf(fxB, 0.0f), (float)(W_ - 1));
    fyB = fminf(fmaxf(fyB, 0.0f), (float)(H_ - 1));
    const int x0B = min((int)fxB, W_ - 2);
    const int y0B = min((int)fyB, H_ - 2);
    const float wxB = fxB - (float)x0B;
    const float wyB = fyB - (float)y0B;
    const float w00B = (1.0f - wyB) * (1.0f - wxB);
    const float w01B = (1.0f - wyB) * wxB;
    const float w10B = wyB * (1.0f - wxB);
    const float w11B = wyB * wxB;

    // ---- 32-bit element offsets (tensor = 100.6M elems < 2^31) ----
    const unsigned ibase = (unsigned)b * (D_ * PLANE_);
    unsigned oA = ibase + (unsigned)y0A * W_ + (unsigned)x0A;
    unsigned oB = ibase + (unsigned)y0B * W_ + (unsigned)x0B;
    unsigned oo = ibase + (unsigned)h * W_ + (unsigned)w;

    #pragma unroll 8
    for (int d = 0; d < D_; ++d) {
        const float a00 = __ldg(img + oA);
        const float a01 = __ldg(img + oA + 1);
        const float a10 = __ldg(img + oA + W_);
        const float a11 = __ldg(img + oA + W_ + 1);
        const float b00 = __ldg(img + oB);
        const float b01 = __ldg(img + oB + 1);
        const float b10 = __ldg(img + oB + W_);
        const float b11 = __ldg(img + oB + W_ + 1);

        float rA = w00A * a00;
        rA = fmaf(w01A, a01, rA);
        rA = fmaf(w10A, a10, rA);
        rA = fmaf(w11A, a11, rA);
        float rB = w00B * b00;
        rB = fmaf(w01B, b01, rB);
        rB = fmaf(w10B, b10, rB);
        rB = fmaf(w11B, b11, rB);

        out[oo] = rA;
        out[oo + 256] = rB;

        oA += PLANE_;
        oB += PLANE_;
        oo += PLANE_;
    }
}

extern "C" void kernel_launch(void* const* d_in, const int* in_sizes, int n_in,
                              void* d_out, int out_size)
{
    const float* img  = (const float*)d_in[0];
    const float* flow = (const float*)d_in[1];
    float* out = (float*)d_out;

    dim3 grid(B_ * H_);                      // 3072
    dim3 block(TPB);
    resample2d_kernel<<<grid, block>>>(img, flow, out);
}